// round 7
// baseline (speedup 1.0000x reference)
#include <cuda_runtime.h>
#include <math.h>

#define T_SAMPLES 128
#define HID 16
#define HPAIRS (HID / 2)

typedef unsigned long long u64;

#define LOG2E 1.4426950408889634f

// ---- packed f32x2 helpers (sm_100+; emits FFMA2 in SASS) ----
__device__ __forceinline__ u64 pack2(float lo, float hi) {
    u64 r; asm("mov.b64 %0, {%1,%2};" : "=l"(r) : "f"(lo), "f"(hi)); return r;
}
__device__ __forceinline__ void unpack2(u64 v, float& lo, float& hi) {
    asm("mov.b64 {%0,%1}, %2;" : "=f"(lo), "=f"(hi) : "l"(v));
}
__device__ __forceinline__ u64 fma2(u64 a, u64 b, u64 c) {
    u64 r; asm("fma.rn.f32x2 %0, %1, %2, %3;" : "=l"(r) : "l"(a), "l"(b), "l"(c));
    return r;
}
__device__ __forceinline__ u64 relu2(u64 v) {
    float lo, hi;
    unpack2(v, lo, hi);
    lo = fmaxf(lo, 0.0f);     // FMNMX -> alu pipe
    hi = fmaxf(hi, 0.0f);
    return pack2(lo, hi);
}
__device__ __forceinline__ float ex2(float x) {
    float r; asm("ex2.approx.f32 %0, %1;" : "=f"(r) : "f"(x)); return r;
}
__device__ __forceinline__ float lg2(float x) {
    float r; asm("lg2.approx.f32 %0, %1;" : "=f"(r) : "f"(x)); return r;
}
__device__ __forceinline__ float rcp(float x) {
    float r; asm("rcp.approx.f32 %0, %1;" : "=f"(r) : "f"(x)); return r;
}

__global__ void __launch_bounds__(64, 4)
nerf_render_kernel(const float* __restrict__ o,
                   const float* __restrict__ d,
                   const float* __restrict__ tnear,
                   const float* __restrict__ tfar,
                   const float* __restrict__ noise,
                   const float* __restrict__ W1,      // (3,16)
                   const float* __restrict__ b1,      // (16)
                   const float* __restrict__ w_sigma, // (16,1)
                   const float* __restrict__ W_rgb,   // (16,3)
                   float* __restrict__ out,           // (N,5)
                   int N)
{
    const int ray = blockIdx.x * blockDim.x + threadIdx.x;
    if (ray >= N) return;

    // ---- per-ray geometry ----
    const float ox = o[3 * ray + 0], oy = o[3 * ray + 1], oz = o[3 * ray + 2];
    const float dx = d[3 * ray + 0], dy = d[3 * ray + 1], dz = d[3 * ray + 2];
    const float dn = sqrtf(dx * dx + dy * dy + dz * dz);
    const float tn = tnear[ray];
    const float tf = tfar[ray];
    const float step = (tf - tn) * (1.0f / (float)T_SAMPLES);

    // ---- fold ray into layer-1: pre_j(t) = A_j + t * B_j ----
    u64 Ap[HPAIRS], Bp[HPAIRS];
    u64 ws2[HPAIRS], wr0_2[HPAIRS], wr1_2[HPAIRS], wr2_2[HPAIRS];
#pragma unroll
    for (int p = 0; p < HPAIRS; p++) {
        const int j = 2 * p;
        const float w1x0 = __ldg(&W1[0 * HID + j]), w1x1 = __ldg(&W1[0 * HID + j + 1]);
        const float w1y0 = __ldg(&W1[1 * HID + j]), w1y1 = __ldg(&W1[1 * HID + j + 1]);
        const float w1z0 = __ldg(&W1[2 * HID + j]), w1z1 = __ldg(&W1[2 * HID + j + 1]);
        const float A0 = fmaf(ox, w1x0, fmaf(oy, w1y0, fmaf(oz, w1z0, __ldg(&b1[j]))));
        const float A1 = fmaf(ox, w1x1, fmaf(oy, w1y1, fmaf(oz, w1z1, __ldg(&b1[j + 1]))));
        const float B0 = fmaf(dx, w1x0, fmaf(dy, w1y0, dz * w1z0));
        const float B1 = fmaf(dx, w1x1, fmaf(dy, w1y1, dz * w1z1));
        Ap[p] = pack2(A0, A1);
        Bp[p] = pack2(B0, B1);
        ws2[p]   = pack2(__ldg(&w_sigma[j]), __ldg(&w_sigma[j + 1]));
        wr0_2[p] = pack2(__ldg(&W_rgb[j * 3 + 0]), __ldg(&W_rgb[(j + 1) * 3 + 0]));
        wr1_2[p] = pack2(__ldg(&W_rgb[j * 3 + 1]), __ldg(&W_rgb[(j + 1) * 3 + 1]));
        wr2_2[p] = pack2(__ldg(&W_rgb[j * 3 + 2]), __ldg(&W_rgb[(j + 1) * 3 + 2]));
    }

    float ts_prev = fmaf(step, noise[ray], tn);

    float Ttr = 1.0f;
    float c0 = 0.f, c1 = 0.f, c2 = 0.f, dep = 0.f, alp = 0.f;

#pragma unroll 8
    for (int t = 1; t <= T_SAMPLES; t++) {
        float ts;
        if (t < T_SAMPLES) {
            const float u = __ldg(&noise[(size_t)t * N + ray]);
            ts = fmaf(step, (float)t + u, tn);
        } else {
            ts = tf;
        }
        const float nk = (ts_prev - ts) * dn;   // -delta*dn

        const u64 tp = pack2(ts_prev, ts_prev);

        u64 accs2 = 0ull, r0p = 0ull, r1p = 0ull, r2p = 0ull;
#pragma unroll
        for (int p = 0; p < HPAIRS; p++) {
            u64 hp = fma2(tp, Bp[p], Ap[p]);   // layer 1: one FFMA2
            hp = relu2(hp);                    // 2x FMNMX (alu pipe)
            accs2 = fma2(hp, ws2[p],   accs2);
            r0p   = fma2(hp, wr0_2[p], r0p);
            r1p   = fma2(hp, wr1_2[p], r1p);
            r2p   = fma2(hp, wr2_2[p], r2p);
        }

        float al, ah, r0l, r0h, r1l, r1h, r2l, r2h;
        unpack2(accs2, al, ah);
        unpack2(r0p, r0l, r0h);
        unpack2(r1p, r1l, r1h);
        unpack2(r2p, r2l, r2h);
        const float acc_s = al + ah;
        const float r0 = r0l + r0h, r1 = r1l + r1h, r2 = r2l + r2h;

        // fused softplus+exp:  e = 2^( -k * log2(1 + 2^(a*log2e)) )
        const float l = lg2(1.0f + ex2(acc_s * LOG2E));
        const float e = ex2(nk * l);
        const float w = Ttr * (1.0f - e);
        Ttr *= e;

        // sigmoids: 1/(1 + 2^(-r*log2e))
        const float s0 = rcp(1.0f + ex2(-r0 * LOG2E));
        const float s1 = rcp(1.0f + ex2(-r1 * LOG2E));
        const float s2 = rcp(1.0f + ex2(-r2 * LOG2E));

        c0  = fmaf(w, s0, c0);
        c1  = fmaf(w, s1, c1);
        c2  = fmaf(w, s2, c2);
        dep = fmaf(w, ts_prev, dep);
        alp += w;

        ts_prev = ts;
    }

    out[5 * ray + 0] = c0;
    out[5 * ray + 1] = c1;
    out[5 * ray + 2] = c2;
    out[5 * ray + 3] = dep;
    out[5 * ray + 4] = alp;
}

extern "C" void kernel_launch(void* const* d_in, const int* in_sizes, int n_in,
                              void* d_out, int out_size)
{
    const float* o       = (const float*)d_in[0];
    const float* d       = (const float*)d_in[1];
    const float* tnear   = (const float*)d_in[2];
    const float* tfar    = (const float*)d_in[3];
    const float* noise   = (const float*)d_in[4];
    const float* W1      = (const float*)d_in[5];
    const float* b1      = (const float*)d_in[6];
    const float* w_sigma = (const float*)d_in[7];
    const float* W_rgb   = (const float*)d_in[8];
    float* out = (float*)d_out;

    const int N = in_sizes[2];  // tnear element count
    const int threads = 64;
    const int blocks = (N + threads - 1) / threads;
    nerf_render_kernel<<<blocks, threads>>>(o, d, tnear, tfar, noise,
                                            W1, b1, w_sigma, W_rgb, out, N);
}

// round 8
// speedup vs baseline: 1.6415x; 1.6415x over previous
#include <cuda_runtime.h>
#include <math.h>

#define T_SAMPLES 128
#define HID 16
#define HPAIRS (HID / 2)

typedef unsigned long long u64;

#define LOG2E 1.4426950408889634f

// ---- packed f32x2 helpers (sm_100+; emits FFMA2 in SASS) ----
__device__ __forceinline__ u64 pack2(float lo, float hi) {
    u64 r; asm("mov.b64 %0, {%1,%2};" : "=l"(r) : "f"(lo), "f"(hi)); return r;
}
__device__ __forceinline__ void unpack2(u64 v, float& lo, float& hi) {
    asm("mov.b64 {%0,%1}, %2;" : "=f"(lo), "=f"(hi) : "l"(v));
}
__device__ __forceinline__ u64 fma2(u64 a, u64 b, u64 c) {
    u64 r; asm("fma.rn.f32x2 %0, %1, %2, %3;" : "=l"(r) : "l"(a), "l"(b), "l"(c));
    return r;
}
__device__ __forceinline__ u64 relu2(u64 v) {
    float lo, hi;
    unpack2(v, lo, hi);
    lo = fmaxf(lo, 0.0f);     // FMNMX -> alu pipe
    hi = fmaxf(hi, 0.0f);
    return pack2(lo, hi);
}
__device__ __forceinline__ float ex2(float x) {
    float r; asm("ex2.approx.f32 %0, %1;" : "=f"(r) : "f"(x)); return r;
}
__device__ __forceinline__ float lg2(float x) {
    float r; asm("lg2.approx.f32 %0, %1;" : "=f"(r) : "f"(x)); return r;
}
__device__ __forceinline__ float rcp(float x) {
    float r; asm("rcp.approx.f32 %0, %1;" : "=f"(r) : "f"(x)); return r;
}

__global__ void __launch_bounds__(128, 3)
nerf_render_kernel(const float* __restrict__ o,
                   const float* __restrict__ d,
                   const float* __restrict__ tnear,
                   const float* __restrict__ tfar,
                   const float* __restrict__ noise,
                   const float* __restrict__ W1,      // (3,16)
                   const float* __restrict__ b1,      // (16)
                   const float* __restrict__ w_sigma, // (16,1)
                   const float* __restrict__ W_rgb,   // (16,3)
                   float* __restrict__ out,           // (N,5)
                   int N)
{
    const int ray = blockIdx.x * blockDim.x + threadIdx.x;
    if (ray >= N) return;

    // ---- per-ray geometry ----
    const float ox = o[3 * ray + 0], oy = o[3 * ray + 1], oz = o[3 * ray + 2];
    const float dx = d[3 * ray + 0], dy = d[3 * ray + 1], dz = d[3 * ray + 2];
    const float dn = sqrtf(dx * dx + dy * dy + dz * dz);
    const float tn = tnear[ray];
    const float tf = tfar[ray];
    const float step = (tf - tn) * (1.0f / (float)T_SAMPLES);

    // ---- fold ray into layer-1: pre_j(t) = A_j + t * B_j ----
    u64 Ap[HPAIRS], Bp[HPAIRS];
    u64 ws2[HPAIRS], wr0_2[HPAIRS], wr1_2[HPAIRS], wr2_2[HPAIRS];
#pragma unroll
    for (int p = 0; p < HPAIRS; p++) {
        const int j = 2 * p;
        const float w1x0 = __ldg(&W1[0 * HID + j]), w1x1 = __ldg(&W1[0 * HID + j + 1]);
        const float w1y0 = __ldg(&W1[1 * HID + j]), w1y1 = __ldg(&W1[1 * HID + j + 1]);
        const float w1z0 = __ldg(&W1[2 * HID + j]), w1z1 = __ldg(&W1[2 * HID + j + 1]);
        const float A0 = fmaf(ox, w1x0, fmaf(oy, w1y0, fmaf(oz, w1z0, __ldg(&b1[j]))));
        const float A1 = fmaf(ox, w1x1, fmaf(oy, w1y1, fmaf(oz, w1z1, __ldg(&b1[j + 1]))));
        const float B0 = fmaf(dx, w1x0, fmaf(dy, w1y0, dz * w1z0));
        const float B1 = fmaf(dx, w1x1, fmaf(dy, w1y1, dz * w1z1));
        Ap[p] = pack2(A0, A1);
        Bp[p] = pack2(B0, B1);
        ws2[p]   = pack2(__ldg(&w_sigma[j]), __ldg(&w_sigma[j + 1]));
        wr0_2[p] = pack2(__ldg(&W_rgb[j * 3 + 0]), __ldg(&W_rgb[(j + 1) * 3 + 0]));
        wr1_2[p] = pack2(__ldg(&W_rgb[j * 3 + 1]), __ldg(&W_rgb[(j + 1) * 3 + 1]));
        wr2_2[p] = pack2(__ldg(&W_rgb[j * 3 + 2]), __ldg(&W_rgb[(j + 1) * 3 + 2]));
    }

    float ts_prev = fmaf(step, noise[ray], tn);

    float Ttr = 1.0f;
    float c0 = 0.f, c1 = 0.f, c2 = 0.f, dep = 0.f, alp = 0.f;

    // two samples per iteration, MLPs manually interleaved (structural ILP-2)
#pragma unroll 2
    for (int t0 = 1; t0 < T_SAMPLES; t0 += 2) {
        // sample a = t0 (always < T_SAMPLES), sample b = t0+1 (== T_SAMPLES on last iter)
        const float ua = __ldg(&noise[(size_t)t0 * N + ray]);
        const float ts_a = fmaf(step, (float)t0 + ua, tn);
        float ts_b;
        if (t0 + 1 < T_SAMPLES) {
            const float ub = __ldg(&noise[(size_t)(t0 + 1) * N + ray]);
            ts_b = fmaf(step, (float)(t0 + 1) + ub, tn);
        } else {
            ts_b = tf;
        }

        const float nk_a = (ts_prev - ts_a) * dn;  // -delta_a * dn, MLP point = ts_prev
        const float nk_b = (ts_a - ts_b) * dn;     // -delta_b * dn, MLP point = ts_a

        const u64 tpa = pack2(ts_prev, ts_prev);
        const u64 tpb = pack2(ts_a, ts_a);

        u64 sa = 0ull, a0 = 0ull, a1 = 0ull, a2 = 0ull;
        u64 sb = 0ull, b0 = 0ull, b1a = 0ull, b2 = 0ull;
#pragma unroll
        for (int p = 0; p < HPAIRS; p++) {
            u64 ha = fma2(tpa, Bp[p], Ap[p]);
            u64 hb = fma2(tpb, Bp[p], Ap[p]);
            ha = relu2(ha);
            hb = relu2(hb);
            sa = fma2(ha, ws2[p],   sa);
            sb = fma2(hb, ws2[p],   sb);
            a0 = fma2(ha, wr0_2[p], a0);
            b0 = fma2(hb, wr0_2[p], b0);
            a1 = fma2(ha, wr1_2[p], a1);
            b1a = fma2(hb, wr1_2[p], b1a);
            a2 = fma2(ha, wr2_2[p], a2);
            b2 = fma2(hb, wr2_2[p], b2);
        }

        float xl, xh;
        unpack2(sa, xl, xh);  const float accs_a = xl + xh;
        unpack2(sb, xl, xh);  const float accs_b = xl + xh;
        unpack2(a0, xl, xh);  const float r0a = xl + xh;
        unpack2(a1, xl, xh);  const float r1a = xl + xh;
        unpack2(a2, xl, xh);  const float r2a = xl + xh;
        unpack2(b0, xl, xh);  const float r0b = xl + xh;
        unpack2(b1a, xl, xh); const float r1b = xl + xh;
        unpack2(b2, xl, xh);  const float r2b = xl + xh;

        // fused softplus+exp:  e = 2^( -k * log2(1 + 2^(a*log2e)) )
        const float la = lg2(1.0f + ex2(accs_a * LOG2E));
        const float lb = lg2(1.0f + ex2(accs_b * LOG2E));
        const float ea = ex2(nk_a * la);
        const float eb = ex2(nk_b * lb);

        const float s0a = rcp(1.0f + ex2(-r0a * LOG2E));
        const float s1a = rcp(1.0f + ex2(-r1a * LOG2E));
        const float s2a = rcp(1.0f + ex2(-r2a * LOG2E));
        const float s0b = rcp(1.0f + ex2(-r0b * LOG2E));
        const float s1b = rcp(1.0f + ex2(-r1b * LOG2E));
        const float s2b = rcp(1.0f + ex2(-r2b * LOG2E));

        const float wa = Ttr * (1.0f - ea);
        const float Ttr_a = Ttr * ea;
        const float wb = Ttr_a * (1.0f - eb);
        Ttr = Ttr_a * eb;

        c0  = fmaf(wa, s0a, fmaf(wb, s0b, c0));
        c1  = fmaf(wa, s1a, fmaf(wb, s1b, c1));
        c2  = fmaf(wa, s2a, fmaf(wb, s2b, c2));
        dep = fmaf(wa, ts_prev, fmaf(wb, ts_a, dep));
        alp += wa + wb;

        ts_prev = ts_b;
    }

    out[5 * ray + 0] = c0;
    out[5 * ray + 1] = c1;
    out[5 * ray + 2] = c2;
    out[5 * ray + 3] = dep;
    out[5 * ray + 4] = alp;
}

extern "C" void kernel_launch(void* const* d_in, const int* in_sizes, int n_in,
                              void* d_out, int out_size)
{
    const float* o       = (const float*)d_in[0];
    const float* d       = (const float*)d_in[1];
    const float* tnear   = (const float*)d_in[2];
    const float* tfar    = (const float*)d_in[3];
    const float* noise   = (const float*)d_in[4];
    const float* W1      = (const float*)d_in[5];
    const float* b1      = (const float*)d_in[6];
    const float* w_sigma = (const float*)d_in[7];
    const float* W_rgb   = (const float*)d_in[8];
    float* out = (float*)d_out;

    const int N = in_sizes[2];  // tnear element count
    const int threads = 128;
    const int blocks = (N + threads - 1) / threads;
    nerf_render_kernel<<<blocks, threads>>>(o, d, tnear, tfar, noise,
                                            W1, b1, w_sigma, W_rgb, out, N);
}